// round 9
// baseline (speedup 1.0000x reference)
#include <cuda_runtime.h>

#define NN 100000
#define NE 1600000
#define FIN 256
#define NH 4
#define NC 64

struct __align__(32) SP { float4 a; float4 p; };   // src-side: a_src + p, one 32B sector

// Scratch (static __device__ — no allocations allowed)
__device__ float  d_W[12 * FIN];   // 12 folded weight vectors: [as0..3, ad0..3, p0..3]
__device__ float  d_cb;            // bias . fc_w + fc_b
__device__ SP     d_sp[NN];        // packed a_src + p
__device__ float4 d_ad[NN];        // per-node a_dst, 4 heads
__device__ float4 d_den[NN];       // softmax denominators per head
__device__ float4 d_num[NN];       // weighted numerators per head

// ---------------------------------------------------------------------------
// K1: fold lin_w with (att_src, att_dst, fc_w) into 12 x 256 vectors + cb.
// ---------------------------------------------------------------------------
__global__ void k_pre(const float* __restrict__ lin_w,
                      const float* __restrict__ att_src,
                      const float* __restrict__ att_dst,
                      const float* __restrict__ bias,
                      const float* __restrict__ fc_w,
                      const float* __restrict__ fc_b) {
    const int j = blockIdx.x;
    const int k = threadIdx.x;   // 0..255 (feature dim)
    if (j < 12) {
        const int g = j >> 2;    // 0 = att_src, 1 = att_dst, 2 = fc_w
        const int h = j & 3;
        const float* coef = (g == 0) ? att_src + h * NC
                          : (g == 1) ? att_dst + h * NC
                                     : fc_w   + h * NC;
        const float* lw = lin_w + (size_t)h * NC * FIN + k;
        float acc = 0.f;
#pragma unroll 8
        for (int c = 0; c < NC; ++c)
            acc += coef[c] * lw[(size_t)c * FIN];
        d_W[j * FIN + k] = acc;
    } else {
        __shared__ float red[256];
        red[k] = bias[k] * fc_w[k];
        __syncthreads();
        for (int s = 128; s; s >>= 1) {
            if (k < s) red[k] += red[k + s];
            __syncthreads();
        }
        if (k == 0) d_cb = red[0] + fc_b[0];
    }
}

// ---------------------------------------------------------------------------
// K2: per-node projections, smem-staged, 2 nodes per thread. (unchanged from
// the 76.2us version)
// ---------------------------------------------------------------------------
__global__ void __launch_bounds__(128) k_proj(const float* __restrict__ x) {
    __shared__ float xs[32][264];
    __shared__ float ws[12 * FIN];

    const int tid = threadIdx.x;
    const int nb  = blockIdx.x * 32;

#pragma unroll
    for (int i = 0; i < 24; ++i)
        ws[tid + i * 128] = d_W[tid + i * 128];

    {
        const float4* xg = (const float4*)(x + (size_t)nb * FIN);
#pragma unroll
        for (int i = 0; i < 16; ++i) {
            const int f4  = tid + i * 128;       // 0..2047
            const int row = f4 >> 6;
            const int c4  = f4 & 63;
            ((float4*)&xs[row][c4 * 4])[0] = xg[row * 64 + c4];
        }
    }
    __syncthreads();

    const int warp = tid >> 5;
    const int lane = tid & 31;
    const int g    = lane >> 3;
    const int s    = lane & 7;
    const int wb   = warp * 8;
    const int n0   = wb + g;
    const int n1   = wb + g + 4;

    float acc0[12], acc1[12];
#pragma unroll
    for (int j = 0; j < 12; ++j) { acc0[j] = 0.f; acc1[j] = 0.f; }

    const float* xr0 = xs[n0];
    const float* xr1 = xs[n1];
#pragma unroll 4
    for (int t = 0; t < 32; ++t) {
        const int k = t * 8 + s;
        const float xv0 = xr0[k];
        const float xv1 = xr1[k];
#pragma unroll
        for (int j = 0; j < 12; ++j) {
            const float w = ws[j * 256 + k];
            acc0[j] += xv0 * w;
            acc1[j] += xv1 * w;
        }
    }
#pragma unroll
    for (int j = 0; j < 12; ++j) {
        acc0[j] += __shfl_xor_sync(0xffffffffu, acc0[j], 4);
        acc0[j] += __shfl_xor_sync(0xffffffffu, acc0[j], 2);
        acc0[j] += __shfl_xor_sync(0xffffffffu, acc0[j], 1);
        acc1[j] += __shfl_xor_sync(0xffffffffu, acc1[j], 4);
        acc1[j] += __shfl_xor_sync(0xffffffffu, acc1[j], 2);
        acc1[j] += __shfl_xor_sync(0xffffffffu, acc1[j], 1);
    }
    if (s == 0) {
        const int nodeA = nb + n0;
        d_sp[nodeA].a = make_float4(acc0[0], acc0[1], acc0[2],  acc0[3]);
        d_ad[nodeA]   = make_float4(acc0[4], acc0[5], acc0[6],  acc0[7]);
        d_sp[nodeA].p = make_float4(acc0[8], acc0[9], acc0[10], acc0[11]);
        d_den[nodeA]  = make_float4(0.f, 0.f, 0.f, 0.f);
        d_num[nodeA]  = make_float4(0.f, 0.f, 0.f, 0.f);

        const int nodeB = nb + n1;
        d_sp[nodeB].a = make_float4(acc1[0], acc1[1], acc1[2],  acc1[3]);
        d_ad[nodeB]   = make_float4(acc1[4], acc1[5], acc1[6],  acc1[7]);
        d_sp[nodeB].p = make_float4(acc1[8], acc1[9], acc1[10], acc1[11]);
        d_den[nodeB]  = make_float4(0.f, 0.f, 0.f, 0.f);
        d_num[nodeB]  = make_float4(0.f, 0.f, 0.f, 0.f);
    }
}

// ---------------------------------------------------------------------------
// K3: edge pass, LANE-PAIRED: 2 lanes per edge, 16 edges per warp-round,
// 2 rounds per warp (32 edges). Even lane loads sp.a, odd lane loads sp.p of
// the SAME node -> the pair shares one 128B line, so the sp gather costs 16
// wavefronts per 16 edges (half of the 1-thread-per-edge scheme). Both lanes
// load d_ad[dst] (same addr -> line dedup). Even lane computes ex, shuffles
// to odd; one RED.v4 instruction covers den (even lanes) + num (odd lanes).
// ---------------------------------------------------------------------------
__global__ void __launch_bounds__(256) k_edge(const int* __restrict__ ei) {
    const int gw   = (blockIdx.x * 256 + threadIdx.x) >> 5;  // global warp id
    const int lane = threadIdx.x & 31;
    const int pair = lane >> 1;        // edge-in-round 0..15
    const int odd  = lane & 1;         // 0: a/den side, 1: p/num side
    const int eb0  = gw * 32;          // 6250 blocks * 8 warps * 32 edges = NE

#pragma unroll
    for (int r = 0; r < 2; ++r) {
        const int eb = eb0 + r * 16;

        // coalesced index fetch: lanes 0-15 -> src row, lanes 16-31 -> dst row
        const int idx = (lane < 16) ? ei[eb + lane] : ei[NE + eb + (lane - 16)];
        const int src = __shfl_sync(0xffffffffu, idx, pair);
        const int dst = __shfl_sync(0xffffffffu, idx, 16 + pair);

        // paired gather: even lane -> sp.a, odd lane -> sp.p (same 128B line)
        const float4 v = *((const float4*)&d_sp[src] + odd);
        const float4 b = d_ad[dst];    // pair loads same address (dedup)

        // even lane: v == a -> ex is valid; odd lane computes garbage, discarded
        float t;
        float4 ex;
        t = v.x + b.x; t = t > 0.f ? t : 0.2f * t; ex.x = __expf(t);
        t = v.y + b.y; t = t > 0.f ? t : 0.2f * t; ex.y = __expf(t);
        t = v.z + b.z; t = t > 0.f ? t : 0.2f * t; ex.z = __expf(t);
        t = v.w + b.w; t = t > 0.f ? t : 0.2f * t; ex.w = __expf(t);

        // broadcast even lane's ex to its odd partner
        const int from = lane & ~1;
        ex.x = __shfl_sync(0xffffffffu, ex.x, from);
        ex.y = __shfl_sync(0xffffffffu, ex.y, from);
        ex.z = __shfl_sync(0xffffffffu, ex.z, from);
        ex.w = __shfl_sync(0xffffffffu, ex.w, from);

        // even lane contributes ex to den; odd lane contributes ex*p to num
        float4 val;
        if (odd) {
            val.x = ex.x * v.x; val.y = ex.y * v.y;
            val.z = ex.z * v.z; val.w = ex.w * v.w;
        } else {
            val = ex;
        }
        float4* tgt = (odd ? d_num : d_den) + dst;
        asm volatile("red.global.add.v4.f32 [%0], {%1,%2,%3,%4};"
                     :: "l"(tgt), "f"(val.x), "f"(val.y), "f"(val.z), "f"(val.w)
                     : "memory");
    }
}

// ---------------------------------------------------------------------------
// K4: finalize. out[n] = cb + sum_h num/(den + 1e-16)  (fast divide)
// ---------------------------------------------------------------------------
__global__ void __launch_bounds__(256) k_final(float* __restrict__ out) {
    const int n = blockIdx.x * blockDim.x + threadIdx.x;
    if (n >= NN) return;
    const float4 d = d_den[n];
    const float4 u = d_num[n];
    out[n] = d_cb
           + __fdividef(u.x, d.x + 1e-16f)
           + __fdividef(u.y, d.y + 1e-16f)
           + __fdividef(u.z, d.z + 1e-16f)
           + __fdividef(u.w, d.w + 1e-16f);
}

extern "C" void kernel_launch(void* const* d_in, const int* in_sizes, int n_in,
                              void* d_out, int out_size) {
    const float* x       = (const float*)d_in[0];
    const int*   ei      = (const int*)d_in[1];
    const float* lin_w   = (const float*)d_in[2];
    const float* att_src = (const float*)d_in[3];
    const float* att_dst = (const float*)d_in[4];
    const float* bias    = (const float*)d_in[5];
    const float* fc_w    = (const float*)d_in[6];
    const float* fc_b    = (const float*)d_in[7];
    float* out = (float*)d_out;

    k_pre  <<<13, 256>>>(lin_w, att_src, att_dst, bias, fc_w, fc_b);
    k_proj <<<NN / 32, 128>>>(x);                 // 3125 blocks, 32 nodes each
    k_edge <<<NE / (32 * 8), 256>>>(ei);          // 6250 blocks, 256 edges each
    k_final<<<(NN + 255) / 256, 256>>>(out);
}

// round 10
// speedup vs baseline: 1.0280x; 1.0280x over previous
#include <cuda_runtime.h>

#define NN 100000
#define NE 1600000
#define FIN 256
#define NH 4
#define NC 64

struct __align__(32) SP { float4 a; float4 p; };   // src-side: a_src + p, one 32B sector

// Scratch (static __device__ — no allocations allowed)
__device__ float  d_W[12 * FIN];   // 12 folded weight vectors: [as0..3, ad0..3, p0..3]
__device__ float  d_cb;            // bias . fc_w + fc_b
__device__ SP     d_sp[NN];        // packed a_src + p
__device__ float4 d_ad[NN];        // per-node a_dst, 4 heads
__device__ float4 d_den[NN];       // softmax denominators per head
__device__ float4 d_num[NN];       // weighted numerators per head

// ---------------------------------------------------------------------------
// K1: fold lin_w with (att_src, att_dst, fc_w) into 12 x 256 vectors + cb.
// ---------------------------------------------------------------------------
__global__ void k_pre(const float* __restrict__ lin_w,
                      const float* __restrict__ att_src,
                      const float* __restrict__ att_dst,
                      const float* __restrict__ bias,
                      const float* __restrict__ fc_w,
                      const float* __restrict__ fc_b) {
    const int j = blockIdx.x;
    const int k = threadIdx.x;   // 0..255 (feature dim)
    if (j < 12) {
        const int g = j >> 2;    // 0 = att_src, 1 = att_dst, 2 = fc_w
        const int h = j & 3;
        const float* coef = (g == 0) ? att_src + h * NC
                          : (g == 1) ? att_dst + h * NC
                                     : fc_w   + h * NC;
        const float* lw = lin_w + (size_t)h * NC * FIN + k;
        float acc = 0.f;
#pragma unroll 8
        for (int c = 0; c < NC; ++c)
            acc += coef[c] * lw[(size_t)c * FIN];
        d_W[j * FIN + k] = acc;
    } else {
        __shared__ float red[256];
        red[k] = bias[k] * fc_w[k];
        __syncthreads();
        for (int s = 128; s; s >>= 1) {
            if (k < s) red[k] += red[k + s];
            __syncthreads();
        }
        if (k == 0) d_cb = red[0] + fc_b[0];
    }
}

// ---------------------------------------------------------------------------
// K2: per-node projections, smem-staged, 4 nodes per thread.
// Block = 128 threads (4 warps) handles 32 nodes. ALL threads stage (float4
// coalesced, high MLP); warps 0-1 compute, 16 nodes each. Lane = (g = lane>>3,
// s = lane&7); thread computes nodes base, base+4, base+8, base+12, so each
// broadcast w-LDS feeds 4 FMAs -> w crossbar = 24 wf/node (was 48).
// Banks (row stride 264 = 8 mod 32): x addr%32 = 8g+s (+8t rotation), all 32
// lanes distinct per m -> conflict-free; w-LDS = 8-address 4-way broadcast.
// ---------------------------------------------------------------------------
__global__ void __launch_bounds__(128) k_proj(const float* __restrict__ x) {
    __shared__ float xs[32][264];
    __shared__ float ws[12 * FIN];

    const int tid = threadIdx.x;
    const int nb  = blockIdx.x * 32;

    // stage w: 3072 floats / 128 threads = 24 each (coalesced)
#pragma unroll
    for (int i = 0; i < 24; ++i)
        ws[tid + i * 128] = d_W[tid + i * 128];

    // stage x: 32 rows x 64 float4 = 2048 float4 / 128 threads = 16 each
    {
        const float4* xg = (const float4*)(x + (size_t)nb * FIN);
#pragma unroll
        for (int i = 0; i < 16; ++i) {
            const int f4  = tid + i * 128;       // 0..2047
            const int row = f4 >> 6;
            const int c4  = f4 & 63;
            ((float4*)&xs[row][c4 * 4])[0] = xg[row * 64 + c4];
        }
    }
    __syncthreads();

    const int warp = tid >> 5;
    if (warp >= 2) return;                       // warps 2,3 only staged
    const int lane = tid & 31;
    const int g    = lane >> 3;
    const int s    = lane & 7;
    const int base = warp * 16 + g;              // nodes base + {0,4,8,12}

    float acc[4][12];
#pragma unroll
    for (int m = 0; m < 4; ++m)
#pragma unroll
        for (int j = 0; j < 12; ++j) acc[m][j] = 0.f;

#pragma unroll 4
    for (int t = 0; t < 32; ++t) {
        const int k = t * 8 + s;
        float xv[4];
#pragma unroll
        for (int m = 0; m < 4; ++m) xv[m] = xs[base + 4 * m][k];
#pragma unroll
        for (int j = 0; j < 12; ++j) {
            const float w = ws[j * 256 + k];
#pragma unroll
            for (int m = 0; m < 4; ++m) acc[m][j] += xv[m] * w;
        }
    }

#pragma unroll
    for (int m = 0; m < 4; ++m)
#pragma unroll
        for (int j = 0; j < 12; ++j) {
            acc[m][j] += __shfl_xor_sync(0xffffffffu, acc[m][j], 4);
            acc[m][j] += __shfl_xor_sync(0xffffffffu, acc[m][j], 2);
            acc[m][j] += __shfl_xor_sync(0xffffffffu, acc[m][j], 1);
        }
    if (s == 0) {
#pragma unroll
        for (int m = 0; m < 4; ++m) {
            const int node = nb + base + 4 * m;
            d_sp[node].a = make_float4(acc[m][0], acc[m][1], acc[m][2],  acc[m][3]);
            d_ad[node]   = make_float4(acc[m][4], acc[m][5], acc[m][6],  acc[m][7]);
            d_sp[node].p = make_float4(acc[m][8], acc[m][9], acc[m][10], acc[m][11]);
            d_den[node]  = make_float4(0.f, 0.f, 0.f, 0.f);
            d_num[node]  = make_float4(0.f, 0.f, 0.f, 0.f);
        }
    }
}

// ---------------------------------------------------------------------------
// K3: edge pass, LANE-PAIRED (unchanged from 76.2us version): 2 lanes per
// edge, 16 edges per warp-round, 2 rounds per warp.
// ---------------------------------------------------------------------------
__global__ void __launch_bounds__(256) k_edge(const int* __restrict__ ei) {
    const int gw   = (blockIdx.x * 256 + threadIdx.x) >> 5;  // global warp id
    const int lane = threadIdx.x & 31;
    const int pair = lane >> 1;        // edge-in-round 0..15
    const int odd  = lane & 1;         // 0: a/den side, 1: p/num side
    const int eb0  = gw * 32;

#pragma unroll
    for (int r = 0; r < 2; ++r) {
        const int eb = eb0 + r * 16;

        const int idx = (lane < 16) ? ei[eb + lane] : ei[NE + eb + (lane - 16)];
        const int src = __shfl_sync(0xffffffffu, idx, pair);
        const int dst = __shfl_sync(0xffffffffu, idx, 16 + pair);

        const float4 v = *((const float4*)&d_sp[src] + odd);
        const float4 b = d_ad[dst];

        float t;
        float4 ex;
        t = v.x + b.x; t = t > 0.f ? t : 0.2f * t; ex.x = __expf(t);
        t = v.y + b.y; t = t > 0.f ? t : 0.2f * t; ex.y = __expf(t);
        t = v.z + b.z; t = t > 0.f ? t : 0.2f * t; ex.z = __expf(t);
        t = v.w + b.w; t = t > 0.f ? t : 0.2f * t; ex.w = __expf(t);

        const int from = lane & ~1;
        ex.x = __shfl_sync(0xffffffffu, ex.x, from);
        ex.y = __shfl_sync(0xffffffffu, ex.y, from);
        ex.z = __shfl_sync(0xffffffffu, ex.z, from);
        ex.w = __shfl_sync(0xffffffffu, ex.w, from);

        float4 val;
        if (odd) {
            val.x = ex.x * v.x; val.y = ex.y * v.y;
            val.z = ex.z * v.z; val.w = ex.w * v.w;
        } else {
            val = ex;
        }
        float4* tgt = (odd ? d_num : d_den) + dst;
        asm volatile("red.global.add.v4.f32 [%0], {%1,%2,%3,%4};"
                     :: "l"(tgt), "f"(val.x), "f"(val.y), "f"(val.z), "f"(val.w)
                     : "memory");
    }
}

// ---------------------------------------------------------------------------
// K4: finalize. out[n] = cb + sum_h num/(den + 1e-16)  (fast divide)
// ---------------------------------------------------------------------------
__global__ void __launch_bounds__(256) k_final(float* __restrict__ out) {
    const int n = blockIdx.x * blockDim.x + threadIdx.x;
    if (n >= NN) return;
    const float4 d = d_den[n];
    const float4 u = d_num[n];
    out[n] = d_cb
           + __fdividef(u.x, d.x + 1e-16f)
           + __fdividef(u.y, d.y + 1e-16f)
           + __fdividef(u.z, d.z + 1e-16f)
           + __fdividef(u.w, d.w + 1e-16f);
}

extern "C" void kernel_launch(void* const* d_in, const int* in_sizes, int n_in,
                              void* d_out, int out_size) {
    const float* x       = (const float*)d_in[0];
    const int*   ei      = (const int*)d_in[1];
    const float* lin_w   = (const float*)d_in[2];
    const float* att_src = (const float*)d_in[3];
    const float* att_dst = (const float*)d_in[4];
    const float* bias    = (const float*)d_in[5];
    const float* fc_w    = (const float*)d_in[6];
    const float* fc_b    = (const float*)d_in[7];
    float* out = (float*)d_out;

    k_pre  <<<13, 256>>>(lin_w, att_src, att_dst, bias, fc_w, fc_b);
    k_proj <<<NN / 32, 128>>>(x);                 // 3125 blocks, 32 nodes each
    k_edge <<<NE / (32 * 8), 256>>>(ei);          // 6250 blocks, 256 edges each
    k_final<<<(NN + 255) / 256, 256>>>(out);
}

// round 11
// speedup vs baseline: 1.0837x; 1.0541x over previous
#include <cuda_runtime.h>

#define NN 100000
#define NE 1600000
#define FIN 256
#define NH 4
#define NC 64

struct __align__(32) SP { float4 a; float4 p; };   // src-side: a_src + p, one 32B sector

// Scratch (static __device__ — no allocations allowed)
// d_W is stored TRANSPOSED: d_W[k*12 + j]  (k = feature 0..255, j = vector 0..11)
__device__ float  d_W[FIN * 12];
__device__ float  d_cb;            // bias . fc_w + fc_b
__device__ SP     d_sp[NN];        // packed a_src + p
__device__ float4 d_ad[NN];        // per-node a_dst, 4 heads
__device__ float4 d_den[NN];       // softmax denominators per head
__device__ float4 d_num[NN];       // weighted numerators per head

// ---------------------------------------------------------------------------
// K1: fold lin_w with (att_src, att_dst, fc_w) into 12 x 256 vectors + cb.
// Output written transposed: d_W[k*12 + j].
// ---------------------------------------------------------------------------
__global__ void k_pre(const float* __restrict__ lin_w,
                      const float* __restrict__ att_src,
                      const float* __restrict__ att_dst,
                      const float* __restrict__ bias,
                      const float* __restrict__ fc_w,
                      const float* __restrict__ fc_b) {
    const int j = blockIdx.x;
    const int k = threadIdx.x;   // 0..255 (feature dim)
    if (j < 12) {
        const int g = j >> 2;    // 0 = att_src, 1 = att_dst, 2 = fc_w
        const int h = j & 3;
        const float* coef = (g == 0) ? att_src + h * NC
                          : (g == 1) ? att_dst + h * NC
                                     : fc_w   + h * NC;
        const float* lw = lin_w + (size_t)h * NC * FIN + k;
        float acc = 0.f;
#pragma unroll 8
        for (int c = 0; c < NC; ++c)
            acc += coef[c] * lw[(size_t)c * FIN];
        d_W[k * 12 + j] = acc;
    } else {
        __shared__ float red[256];
        red[k] = bias[k] * fc_w[k];
        __syncthreads();
        for (int s = 128; s; s >>= 1) {
            if (k < s) red[k] += red[k + s];
            __syncthreads();
        }
        if (k == 0) d_cb = red[0] + fc_b[0];
    }
}

// ---------------------------------------------------------------------------
// K2: per-node projections, smem-staged, 4 nodes per thread, j-paired f32x2.
// Block = 128 threads (4 warps) handles 32 nodes; all threads stage, warps
// 0-1 compute. Weights live transposed in smem (ws[k*12+j]) so one LDS.64
// fetches the (2i, 2i+1) weight pair as packed f32x2; x is replicated into
// both halves. Per (t, thread): 4 x-LDS + 6 w-LDS.64 + 24 fma.f32x2
// (= 48 scalar FMAs) -> FFMA-issue floor halved vs scalar version.
// Banks: x addr%32 = 8g+s (+8t rot) all distinct; w-LDS.64 banks {12s,12s+1}
// all distinct, 8-address broadcast -> conflict-free.
// ---------------------------------------------------------------------------
__global__ void __launch_bounds__(128) k_proj(const float* __restrict__ x) {
    __shared__ float xs[32][264];
    __shared__ float ws[FIN * 12];

    const int tid = threadIdx.x;
    const int nb  = blockIdx.x * 32;

    // stage w (already transposed in d_W): 3072 floats / 128 = 24 each
#pragma unroll
    for (int i = 0; i < 24; ++i)
        ws[tid + i * 128] = d_W[tid + i * 128];

    // stage x: 32 rows x 64 float4 = 2048 float4 / 128 threads = 16 each
    {
        const float4* xg = (const float4*)(x + (size_t)nb * FIN);
#pragma unroll
        for (int i = 0; i < 16; ++i) {
            const int f4  = tid + i * 128;       // 0..2047
            const int row = f4 >> 6;
            const int c4  = f4 & 63;
            ((float4*)&xs[row][c4 * 4])[0] = xg[row * 64 + c4];
        }
    }
    __syncthreads();

    const int warp = tid >> 5;
    if (warp >= 2) return;                       // warps 2,3 only staged
    const int lane = tid & 31;
    const int g    = lane >> 3;
    const int s    = lane & 7;
    const int base = warp * 16 + g;              // nodes base + {0,4,8,12}

    // accp[i][m]: packed f32x2 accumulator for heads (2i, 2i+1), node m
    unsigned long long accp[6][4];
#pragma unroll
    for (int i = 0; i < 6; ++i)
#pragma unroll
        for (int m = 0; m < 4; ++m) accp[i][m] = 0ull;

#pragma unroll 4
    for (int t = 0; t < 32; ++t) {
        const int k = t * 8 + s;
        unsigned long long x2[4];
#pragma unroll
        for (int m = 0; m < 4; ++m) {
            const float xv = xs[base + 4 * m][k];
            asm("mov.b64 %0,{%1,%1};" : "=l"(x2[m]) : "f"(xv));
        }
        const unsigned long long* wrow =
            (const unsigned long long*)(ws + k * 12);
#pragma unroll
        for (int i = 0; i < 6; ++i) {
            const unsigned long long w2 = wrow[i];   // heads (2i, 2i+1)
#pragma unroll
            for (int m = 0; m < 4; ++m)
                asm("fma.rn.f32x2 %0,%1,%2,%0;"
                    : "+l"(accp[i][m]) : "l"(x2[m]), "l"(w2));
        }
    }

    // unpack to scalar acc[m][j]
    float acc[4][12];
#pragma unroll
    for (int i = 0; i < 6; ++i)
#pragma unroll
        for (int m = 0; m < 4; ++m)
            asm("mov.b64 {%0,%1},%2;"
                : "=f"(acc[m][2 * i]), "=f"(acc[m][2 * i + 1]) : "l"(accp[i][m]));

#pragma unroll
    for (int m = 0; m < 4; ++m)
#pragma unroll
        for (int j = 0; j < 12; ++j) {
            acc[m][j] += __shfl_xor_sync(0xffffffffu, acc[m][j], 4);
            acc[m][j] += __shfl_xor_sync(0xffffffffu, acc[m][j], 2);
            acc[m][j] += __shfl_xor_sync(0xffffffffu, acc[m][j], 1);
        }
    if (s == 0) {
#pragma unroll
        for (int m = 0; m < 4; ++m) {
            const int node = nb + base + 4 * m;
            d_sp[node].a = make_float4(acc[m][0], acc[m][1], acc[m][2],  acc[m][3]);
            d_ad[node]   = make_float4(acc[m][4], acc[m][5], acc[m][6],  acc[m][7]);
            d_sp[node].p = make_float4(acc[m][8], acc[m][9], acc[m][10], acc[m][11]);
            d_den[node]  = make_float4(0.f, 0.f, 0.f, 0.f);
            d_num[node]  = make_float4(0.f, 0.f, 0.f, 0.f);
        }
    }
}

// ---------------------------------------------------------------------------
// K3: edge pass, LANE-PAIRED (unchanged): 2 lanes per edge, 16 edges per
// warp-round, 2 rounds per warp.
// ---------------------------------------------------------------------------
__global__ void __launch_bounds__(256) k_edge(const int* __restrict__ ei) {
    const int gw   = (blockIdx.x * 256 + threadIdx.x) >> 5;  // global warp id
    const int lane = threadIdx.x & 31;
    const int pair = lane >> 1;        // edge-in-round 0..15
    const int odd  = lane & 1;         // 0: a/den side, 1: p/num side
    const int eb0  = gw * 32;

#pragma unroll
    for (int r = 0; r < 2; ++r) {
        const int eb = eb0 + r * 16;

        const int idx = (lane < 16) ? ei[eb + lane] : ei[NE + eb + (lane - 16)];
        const int src = __shfl_sync(0xffffffffu, idx, pair);
        const int dst = __shfl_sync(0xffffffffu, idx, 16 + pair);

        const float4 v = *((const float4*)&d_sp[src] + odd);
        const float4 b = d_ad[dst];

        float t;
        float4 ex;
        t = v.x + b.x; t = t > 0.f ? t : 0.2f * t; ex.x = __expf(t);
        t = v.y + b.y; t = t > 0.f ? t : 0.2f * t; ex.y = __expf(t);
        t = v.z + b.z; t = t > 0.f ? t : 0.2f * t; ex.z = __expf(t);
        t = v.w + b.w; t = t > 0.f ? t : 0.2f * t; ex.w = __expf(t);

        const int from = lane & ~1;
        ex.x = __shfl_sync(0xffffffffu, ex.x, from);
        ex.y = __shfl_sync(0xffffffffu, ex.y, from);
        ex.z = __shfl_sync(0xffffffffu, ex.z, from);
        ex.w = __shfl_sync(0xffffffffu, ex.w, from);

        float4 val;
        if (odd) {
            val.x = ex.x * v.x; val.y = ex.y * v.y;
            val.z = ex.z * v.z; val.w = ex.w * v.w;
        } else {
            val = ex;
        }
        float4* tgt = (odd ? d_num : d_den) + dst;
        asm volatile("red.global.add.v4.f32 [%0], {%1,%2,%3,%4};"
                     :: "l"(tgt), "f"(val.x), "f"(val.y), "f"(val.z), "f"(val.w)
                     : "memory");
    }
}

// ---------------------------------------------------------------------------
// K4: finalize. out[n] = cb + sum_h num/(den + 1e-16)  (fast divide)
// ---------------------------------------------------------------------------
__global__ void __launch_bounds__(256) k_final(float* __restrict__ out) {
    const int n = blockIdx.x * blockDim.x + threadIdx.x;
    if (n >= NN) return;
    const float4 d = d_den[n];
    const float4 u = d_num[n];
    out[n] = d_cb
           + __fdividef(u.x, d.x + 1e-16f)
           + __fdividef(u.y, d.y + 1e-16f)
           + __fdividef(u.z, d.z + 1e-16f)
           + __fdividef(u.w, d.w + 1e-16f);
}

extern "C" void kernel_launch(void* const* d_in, const int* in_sizes, int n_in,
                              void* d_out, int out_size) {
    const float* x       = (const float*)d_in[0];
    const int*   ei      = (const int*)d_in[1];
    const float* lin_w   = (const float*)d_in[2];
    const float* att_src = (const float*)d_in[3];
    const float* att_dst = (const float*)d_in[4];
    const float* bias    = (const float*)d_in[5];
    const float* fc_w    = (const float*)d_in[6];
    const float* fc_b    = (const float*)d_in[7];
    float* out = (float*)d_out;

    k_pre  <<<13, 256>>>(lin_w, att_src, att_dst, bias, fc_w, fc_b);
    k_proj <<<NN / 32, 128>>>(x);                 // 3125 blocks, 32 nodes each
    k_edge <<<NE / (32 * 8), 256>>>(ei);          // 6250 blocks, 256 edges each
    k_final<<<(NN + 255) / 256, 256>>>(out);
}

// round 12
// speedup vs baseline: 1.1278x; 1.0407x over previous
#include <cuda_runtime.h>

#define NN 100000
#define NE 1600000
#define FIN 256
#define NH 4
#define NC 64

struct __align__(32) SP { float4 a;   float4 p;   };  // src-side: a_src + p
struct __align__(32) DN { float4 den; float4 num; };  // dst-side accumulators

// Scratch (static __device__ — no allocations allowed)
// d_W is stored TRANSPOSED: d_W[k*12 + j]  (k = feature 0..255, j = vector 0..11)
__device__ float  d_W[FIN * 12];
__device__ float  d_cb;            // bias . fc_w + fc_b
__device__ SP     d_sp[NN];        // packed a_src + p
__device__ float4 d_ad[NN];        // per-node a_dst, 4 heads
__device__ DN     d_dn[NN];        // packed den + num

// ---------------------------------------------------------------------------
// K1: fold lin_w with (att_src, att_dst, fc_w) into 12 x 256 vectors + cb.
// Output written transposed: d_W[k*12 + j].
// ---------------------------------------------------------------------------
__global__ void k_pre(const float* __restrict__ lin_w,
                      const float* __restrict__ att_src,
                      const float* __restrict__ att_dst,
                      const float* __restrict__ bias,
                      const float* __restrict__ fc_w,
                      const float* __restrict__ fc_b) {
    const int j = blockIdx.x;
    const int k = threadIdx.x;   // 0..255 (feature dim)
    if (j < 12) {
        const int g = j >> 2;    // 0 = att_src, 1 = att_dst, 2 = fc_w
        const int h = j & 3;
        const float* coef = (g == 0) ? att_src + h * NC
                          : (g == 1) ? att_dst + h * NC
                                     : fc_w   + h * NC;
        const float* lw = lin_w + (size_t)h * NC * FIN + k;
        float acc = 0.f;
#pragma unroll 8
        for (int c = 0; c < NC; ++c)
            acc += coef[c] * lw[(size_t)c * FIN];
        d_W[k * 12 + j] = acc;
    } else {
        __shared__ float red[256];
        red[k] = bias[k] * fc_w[k];
        __syncthreads();
        for (int s = 128; s; s >>= 1) {
            if (k < s) red[k] += red[k + s];
            __syncthreads();
        }
        if (k == 0) d_cb = red[0] + fc_b[0];
    }
}

// ---------------------------------------------------------------------------
// K2: per-node projections, smem-staged, 4 nodes per thread, j-paired f32x2.
// (unchanged from the 70.4us version except accumulator init targets d_dn)
// ---------------------------------------------------------------------------
__global__ void __launch_bounds__(128) k_proj(const float* __restrict__ x) {
    __shared__ float xs[32][264];
    __shared__ float ws[FIN * 12];

    const int tid = threadIdx.x;
    const int nb  = blockIdx.x * 32;

#pragma unroll
    for (int i = 0; i < 24; ++i)
        ws[tid + i * 128] = d_W[tid + i * 128];

    {
        const float4* xg = (const float4*)(x + (size_t)nb * FIN);
#pragma unroll
        for (int i = 0; i < 16; ++i) {
            const int f4  = tid + i * 128;       // 0..2047
            const int row = f4 >> 6;
            const int c4  = f4 & 63;
            ((float4*)&xs[row][c4 * 4])[0] = xg[row * 64 + c4];
        }
    }
    __syncthreads();

    const int warp = tid >> 5;
    if (warp >= 2) return;                       // warps 2,3 only staged
    const int lane = tid & 31;
    const int g    = lane >> 3;
    const int s    = lane & 7;
    const int base = warp * 16 + g;              // nodes base + {0,4,8,12}

    unsigned long long accp[6][4];
#pragma unroll
    for (int i = 0; i < 6; ++i)
#pragma unroll
        for (int m = 0; m < 4; ++m) accp[i][m] = 0ull;

#pragma unroll 4
    for (int t = 0; t < 32; ++t) {
        const int k = t * 8 + s;
        unsigned long long x2[4];
#pragma unroll
        for (int m = 0; m < 4; ++m) {
            const float xv = xs[base + 4 * m][k];
            asm("mov.b64 %0,{%1,%1};" : "=l"(x2[m]) : "f"(xv));
        }
        const unsigned long long* wrow =
            (const unsigned long long*)(ws + k * 12);
#pragma unroll
        for (int i = 0; i < 6; ++i) {
            const unsigned long long w2 = wrow[i];   // heads (2i, 2i+1)
#pragma unroll
            for (int m = 0; m < 4; ++m)
                asm("fma.rn.f32x2 %0,%1,%2,%0;"
                    : "+l"(accp[i][m]) : "l"(x2[m]), "l"(w2));
        }
    }

    float acc[4][12];
#pragma unroll
    for (int i = 0; i < 6; ++i)
#pragma unroll
        for (int m = 0; m < 4; ++m)
            asm("mov.b64 {%0,%1},%2;"
                : "=f"(acc[m][2 * i]), "=f"(acc[m][2 * i + 1]) : "l"(accp[i][m]));

#pragma unroll
    for (int m = 0; m < 4; ++m)
#pragma unroll
        for (int j = 0; j < 12; ++j) {
            acc[m][j] += __shfl_xor_sync(0xffffffffu, acc[m][j], 4);
            acc[m][j] += __shfl_xor_sync(0xffffffffu, acc[m][j], 2);
            acc[m][j] += __shfl_xor_sync(0xffffffffu, acc[m][j], 1);
        }
    if (s == 0) {
#pragma unroll
        for (int m = 0; m < 4; ++m) {
            const int node = nb + base + 4 * m;
            d_sp[node].a = make_float4(acc[m][0], acc[m][1], acc[m][2],  acc[m][3]);
            d_ad[node]   = make_float4(acc[m][4], acc[m][5], acc[m][6],  acc[m][7]);
            d_sp[node].p = make_float4(acc[m][8], acc[m][9], acc[m][10], acc[m][11]);
            d_dn[node].den = make_float4(0.f, 0.f, 0.f, 0.f);
            d_dn[node].num = make_float4(0.f, 0.f, 0.f, 0.f);
        }
    }
}

// ---------------------------------------------------------------------------
// K3: edge pass, LANE-PAIRED: 2 lanes per edge, 16 edges per warp-round,
// 2 rounds per warp. Even lane REDs den, odd lane REDs num — adjacent 16B
// addresses within one 32B DN struct (one accumulator line per dst).
// ---------------------------------------------------------------------------
__global__ void __launch_bounds__(256) k_edge(const int* __restrict__ ei) {
    const int gw   = (blockIdx.x * 256 + threadIdx.x) >> 5;  // global warp id
    const int lane = threadIdx.x & 31;
    const int pair = lane >> 1;        // edge-in-round 0..15
    const int odd  = lane & 1;         // 0: a/den side, 1: p/num side
    const int eb0  = gw * 32;

#pragma unroll
    for (int r = 0; r < 2; ++r) {
        const int eb = eb0 + r * 16;

        const int idx = (lane < 16) ? ei[eb + lane] : ei[NE + eb + (lane - 16)];
        const int src = __shfl_sync(0xffffffffu, idx, pair);
        const int dst = __shfl_sync(0xffffffffu, idx, 16 + pair);

        const float4 v = *((const float4*)&d_sp[src] + odd);
        const float4 b = d_ad[dst];

        float t;
        float4 ex;
        t = v.x + b.x; t = t > 0.f ? t : 0.2f * t; ex.x = __expf(t);
        t = v.y + b.y; t = t > 0.f ? t : 0.2f * t; ex.y = __expf(t);
        t = v.z + b.z; t = t > 0.f ? t : 0.2f * t; ex.z = __expf(t);
        t = v.w + b.w; t = t > 0.f ? t : 0.2f * t; ex.w = __expf(t);

        const int from = lane & ~1;
        ex.x = __shfl_sync(0xffffffffu, ex.x, from);
        ex.y = __shfl_sync(0xffffffffu, ex.y, from);
        ex.z = __shfl_sync(0xffffffffu, ex.z, from);
        ex.w = __shfl_sync(0xffffffffu, ex.w, from);

        float4 val;
        if (odd) {
            val.x = ex.x * v.x; val.y = ex.y * v.y;
            val.z = ex.z * v.z; val.w = ex.w * v.w;
        } else {
            val = ex;
        }
        float4* tgt = (float4*)&d_dn[dst] + odd;   // den (even) / num (odd)
        asm volatile("red.global.add.v4.f32 [%0], {%1,%2,%3,%4};"
                     :: "l"(tgt), "f"(val.x), "f"(val.y), "f"(val.z), "f"(val.w)
                     : "memory");
    }
}

// ---------------------------------------------------------------------------
// K4: finalize. out[n] = cb + sum_h num/(den + 1e-16)  (fast divide)
// den+num now share one 32B region -> single line per node.
// ---------------------------------------------------------------------------
__global__ void __launch_bounds__(256) k_final(float* __restrict__ out) {
    const int n = blockIdx.x * blockDim.x + threadIdx.x;
    if (n >= NN) return;
    const float4 d = d_dn[n].den;
    const float4 u = d_dn[n].num;
    out[n] = d_cb
           + __fdividef(u.x, d.x + 1e-16f)
           + __fdividef(u.y, d.y + 1e-16f)
           + __fdividef(u.z, d.z + 1e-16f)
           + __fdividef(u.w, d.w + 1e-16f);
}

extern "C" void kernel_launch(void* const* d_in, const int* in_sizes, int n_in,
                              void* d_out, int out_size) {
    const float* x       = (const float*)d_in[0];
    const int*   ei      = (const int*)d_in[1];
    const float* lin_w   = (const float*)d_in[2];
    const float* att_src = (const float*)d_in[3];
    const float* att_dst = (const float*)d_in[4];
    const float* bias    = (const float*)d_in[5];
    const float* fc_w    = (const float*)d_in[6];
    const float* fc_b    = (const float*)d_in[7];
    float* out = (float*)d_out;

    k_pre  <<<13, 256>>>(lin_w, att_src, att_dst, bias, fc_w, fc_b);
    k_proj <<<NN / 32, 128>>>(x);                 // 3125 blocks, 32 nodes each
    k_edge <<<NE / (32 * 8), 256>>>(ei);          // 6250 blocks, 256 edges each
    k_final<<<(NN + 255) / 256, 256>>>(out);
}